// round 13
// baseline (speedup 1.0000x reference)
#include <cuda_runtime.h>
#include <cuda_bf16.h>

// Problem constants (from reference): B=128, T=200, V=10, F=256
#define V 10
#define VV 100
#define F 256
#define F4 64              // float4 per row
#define GPF4 640           // float4 per graph
#define NT 256

#define GPS 8              // graphs per block (== warps: 1 graph per warp in tail)

__global__ __launch_bounds__(NT, 6)
void graph_embed_kernel(const float* __restrict__ end_output,
                        const float* __restrict__ S,
                        const float* __restrict__ mul,
                        const float* __restrict__ bias,
                        const float* __restrict__ means,
                        const float* __restrict__ stds,
                        const float* __restrict__ emb_in,
                        const float* __restrict__ emb_out,
                        const float* __restrict__ emb3,
                        const float* __restrict__ emb4,
                        float* __restrict__ out,
                        float* __restrict__ out_att,
                        int graphs)
{
    const int tid = threadIdx.x;
    const int g0  = blockIdx.x * GPS;

    __shared__ float shf[GPS * VV];      // symmetrized S (prologue) -> FW dist (tail)
    __shared__ float scomb[V * F];       // comb table for streaming
    __shared__ float stab[3 * VV];       // mul | emb3 | emb4
    __shared__ int   shi[GPS * V];       // degrees
    __shared__ short shs[2 * GPS * VV];  // si | ei

    // ================= PROLOGUE =================
    const float* Sg = S + (size_t)g0 * VV;
    const int nloc = min(GPS, graphs - g0) * VV;
    // symmetrize S into shared ONCE: shf[l,i,j] = min(S[l,i,j], S[l,j,i])
    for (int u = tid; u < nloc; u += NT) {
        int e = u % VV;
        int l = u / VV;
        int ii = e / V, jj = e % V;
        shf[u] = fminf(__ldg(&Sg[u]), __ldg(&Sg[l * VV + jj * V + ii]));
    }
    // comb[d][f] = emb_in[d,f] + emb_out[d,f] (rows 0..9, L1-hot per SM)
    #pragma unroll
    for (int c = 0; c < V * F / NT; c++) {
        int u = tid + c * NT;
        scomb[u] = __ldg(&emb_in[u]) + __ldg(&emb_out[u]);
    }
    // stage small tables
    if (tid < VV)           stab[tid]           = __ldg(&mul[tid]);
    else if (tid < 2 * VV)  stab[tid]           = __ldg(&emb3[tid - VV]);
    else if (tid < 3 * VV)  stab[tid]           = __ldg(&emb4[tid - 2 * VV]);
    __syncthreads();
    // degrees from the symmetrized matrix (fminf idempotent -> identical values)
    if (tid < GPS * V) {
        int l = tid / V, v = tid % V;
        if (g0 + l < graphs) {
            const float* sl = shf + l * VV;
            float dsum = 0.0f;
            #pragma unroll
            for (int ii = 0; ii < V; ii++) dsum += sl[ii * V + v];
            shi[tid] = (int)dsum;                 // trunc toward zero, >= 0
        }
    }
    __syncthreads();

    // ================= STREAMING PHASE =================
    const float4* eo4  = (const float4*)(end_output + (size_t)g0 * (V * F));
    float4*       o4   = (float4*)(out + (size_t)g0 * (V * F));
    const float4* cmb4 = (const float4*)scomb;

    if (g0 + GPS <= graphs) {
        // fast path: 4 chunks, each front-batched with 5 loads
        float4 e[5];
        #pragma unroll
        for (int c = 0; c < 4; c++) {
            #pragma unroll
            for (int it = 0; it < 5; it++)
                e[it] = __ldcs(&eo4[tid + (c * 5 + it) * NT]);
            #pragma unroll
            for (int it = 0; it < 5; it++) {
                int idx = tid + (c * 5 + it) * NT;           // 0..5119
                int d   = shi[idx >> 6];
                float4 cv = cmb4[d * F4 + (idx & (F4 - 1))]; // LDS.128
                float4 r;
                r.x = e[it].x + cv.x; r.y = e[it].y + cv.y;
                r.z = e[it].z + cv.z; r.w = e[it].w + cv.w;
                __stcs(&o4[idx], r);
            }
        }
    } else {
        const int nf4 = (graphs - g0) * GPF4;
        for (int it = 0; it < GPS * GPF4 / NT; it++) {
            int idx = tid + it * NT;
            if (idx < nf4) {
                int d   = shi[idx >> 6];
                float4 ev = __ldcs(&eo4[idx]);
                float4 cv = cmb4[d * F4 + (idx & (F4 - 1))];
                float4 r;
                r.x = ev.x + cv.x; r.y = ev.y + cv.y;
                r.z = ev.z + cv.z; r.w = ev.w + cv.w;
                __stcs(&o4[idx], r);
            }
        }
    }

    // ================= GRAPH TAIL: 1 warp per graph =================
    // Warp w works only on shf[w*VV .. w*VV+99], written before the prologue
    // __syncthreads -> no extra block sync needed here.
    const int w    = tid >> 5;
    const int lane = tid & 31;
    const int g    = g0 + w;
    if (g >= graphs) return;

    float* ds  = shf + w * VV;
    short* sim = shs + w * VV;
    short* eim = shs + GPS * VV + w * VV;
    const float* mul_s  = stab;
    const float* emb3_s = stab + VV;
    const float* emb4_s = stab + 2 * VV;

    int   iiA[4], jjA[4];
    bool  act[4];
    float ef[4], spv[4], dsown[4];
    const float a = sqrtf(2.0f * 3.14159f);       // PI as written in source

    #pragma unroll
    for (int r = 0; r < 4; r++) {
        int e = lane + 32 * r;
        act[r] = (e < VV);
        int e2 = act[r] ? e : 0;
        iiA[r] = e2 / V; jjA[r] = e2 % V;
        spv[r] = 0.0f;
        float x = __ldg(&bias[e2]);
        #pragma unroll
        for (int m = 0; m < V; m++)
            x += ds[iiA[r] * V + m] * mul_s[m * V + jjA[r]];
        float sd = __ldg(&stds[jjA[r]]);
        float z  = __fdividef(x - __ldg(&means[jjA[r]]), sd);
        float tmp = __fdividef(__expf(-0.5f * z * z), a * sd);
        float sg  = __fdividef(1.0f, 1.0f + __expf(-tmp));
        // tanh(sg) = (e^{2sg}-1)/(e^{2sg}+1)
        float E = __expf(2.0f * sg);
        ef[r] = __fdividef(E - 1.0f, E + 1.0f);
        dsown[r] = ds[e2];
    }
    __syncwarp();

    // Floyd-Warshall with update-indicator accumulation.
    // All dists >= 0 (S in [0,1)), so iteration k never writes row k or
    // column k (the only cells it reads) -> single sync per iteration.
    #pragma unroll
    for (int k = 0; k < V; k++) {
        float dik[4], dkj[4];
        #pragma unroll
        for (int r = 0; r < 4; r++) {
            dik[r] = ds[iiA[r] * V + k];
            dkj[r] = ds[k * V + jjA[r]];
        }
        #pragma unroll
        for (int r = 0; r < 4; r++) {
            if (act[r]) {
                float temp = dik[r] + dkj[r];
                if (temp < dsown[r]) {            // == (new != dist)
                    dsown[r] = temp;
                    ds[lane + 32 * r] = temp;
                    spv[r] += ef[r];
                }
            }
        }
        __syncwarp();
    }

    #pragma unroll
    for (int r = 0; r < 4; r++) {
        if (act[r]) {
            int Si = (int)dsown[r]; Si = min(max(Si, 0), V - 1);
            int Ei = (int)spv[r];   Ei = min(max(Ei, 0), V - 1);
            sim[lane + 32 * r] = (short)Si;
            eim[lane + 32 * r] = (short)Ei;
        }
    }
    __syncwarp();

    // atten_bias[g, i, c] = sum_j ( emb3[si[i,j], c] + emb4[ei[i,j], c] )
    #pragma unroll
    for (int r = 0; r < 4; r++) {
        int o = lane + 32 * r;
        if (o < VV) {
            int i2 = o / V, c = o % V;
            float acc0 = 0.0f, acc1 = 0.0f;
            #pragma unroll
            for (int j2 = 0; j2 < V; j2 += 2) {
                acc0 += emb3_s[sim[i2 * V + j2] * V + c]
                      + emb4_s[eim[i2 * V + j2] * V + c];
                acc1 += emb3_s[sim[i2 * V + j2 + 1] * V + c]
                      + emb4_s[eim[i2 * V + j2 + 1] * V + c];
            }
            out_att[(size_t)g * VV + o] = acc0 + acc1;
        }
    }
}

extern "C" void kernel_launch(void* const* d_in, const int* in_sizes, int n_in,
                              void* d_out, int out_size)
{
    const float* end_output = (const float*)d_in[0];   // (B,T,V,F)
    const float* S          = (const float*)d_in[1];   // (B,T,V,V)
    const float* mul_       = (const float*)d_in[2];   // (V,V)
    const float* bias_      = (const float*)d_in[3];   // (V,V)
    const float* means_     = (const float*)d_in[4];   // (1,V)
    const float* stds_      = (const float*)d_in[5];   // (1,V)
    const float* emb_in_    = (const float*)d_in[6];   // (F,F)
    const float* emb_out_   = (const float*)d_in[7];   // (F,F)
    const float* emb3_      = (const float*)d_in[8];   // (V,V)
    const float* emb4_      = (const float*)d_in[9];   // (V,V)

    float* out = (float*)d_out;
    const int graphs = in_sizes[1] / VV;               // B*T
    float* out_att = out + (size_t)in_sizes[0];        // atten_bias after outputs

    int nb = (graphs + GPS - 1) / GPS;
    graph_embed_kernel<<<nb, NT>>>(
        end_output, S, mul_, bias_, means_, stds_,
        emb_in_, emb_out_, emb3_, emb4_, out, out_att, graphs);
}

// round 15
// speedup vs baseline: 1.0701x; 1.0701x over previous
#include <cuda_runtime.h>
#include <cuda_bf16.h>

// Problem constants (from reference): B=128, T=200, V=10, F=256
#define V 10
#define VV 100
#define F 256
#define F4 64              // float4 per row
#define GPF4 640           // float4 per graph
#define NT 256

#define GPS 8              // graphs per streaming block (20 stream iters)
#define GPG 8              // graphs per graph block (1 per warp)

__global__ __launch_bounds__(NT, 8)
void graph_embed_kernel(const float* __restrict__ end_output,
                        const float* __restrict__ S,
                        const float* __restrict__ mul,
                        const float* __restrict__ bias,
                        const float* __restrict__ means,
                        const float* __restrict__ stds,
                        const float* __restrict__ emb_in,
                        const float* __restrict__ emb_out,
                        const float* __restrict__ emb3,
                        const float* __restrict__ emb4,
                        float* __restrict__ out,
                        float* __restrict__ out_att,
                        int graphs, int nsb, int interleave)
{
    const int bid = blockIdx.x;
    const int tid = threadIdx.x;

    __shared__ float shf[GPG * VV];      // 800 floats: S stage (stream) / dist (graph)
    __shared__ float scomb[V * F];       // stream: comb table | graph: mul/emb3/emb4 stage
    __shared__ int   shi[GPS * V];       // degrees (stream)
    __shared__ short shs[2 * GPG * VV];  // si|ei (graph)

    // role mapping: 1:1 interleave when block counts match
    int role, rbid;
    if (interleave) { role = bid & 1; rbid = bid >> 1; }
    else { if (bid < nsb) { role = 0; rbid = bid; } else { role = 1; rbid = bid - nsb; } }

    if (role == 0) {
        // ================= STREAMING BLOCK: 8 graphs =================
        const int g0 = rbid * GPS;
        const float* Sg = S + (size_t)g0 * VV;
        const int nloc = min(GPS, graphs - g0) * VV;
        for (int u = tid; u < nloc; u += NT)
            shf[u] = Sg[u];
        // build comb[d][f] = emb_in[d,f] + emb_out[d,f] (rows 0..9, L1-hot per SM)
        #pragma unroll
        for (int c = 0; c < V * F / NT; c++) {
            int u = tid + c * NT;
            scomb[u] = __ldg(&emb_in[u]) + __ldg(&emb_out[u]);
        }
        __syncthreads();
        if (tid < GPS * V) {
            int l = tid / V, v = tid % V;
            if (g0 + l < graphs) {
                const float* sl = shf + l * VV;
                float dsum = 0.0f;
                #pragma unroll
                for (int ii = 0; ii < V; ii++)
                    dsum += fminf(sl[ii * V + v], sl[v * V + ii]);
                shi[tid] = (int)dsum;               // trunc toward zero, >= 0
            }
        }
        __syncthreads();

        const float4* eo4  = (const float4*)(end_output + (size_t)g0 * (V * F));
        float4*       o4   = (float4*)(out + (size_t)g0 * (V * F));
        const float4* cmb4 = (const float4*)scomb;

        if (g0 + GPS <= graphs) {
            // fast path: 5 chunks, each front-batched with 4 loads (16 regs)
            float4 e[4];
            #pragma unroll
            for (int c = 0; c < 5; c++) {
                #pragma unroll
                for (int it = 0; it < 4; it++)
                    e[it] = __ldcs(&eo4[tid + (c * 4 + it) * NT]);
                #pragma unroll
                for (int it = 0; it < 4; it++) {
                    int idx = tid + (c * 4 + it) * NT;           // 0..5119
                    int d   = shi[idx >> 6];
                    float4 cv = cmb4[d * F4 + (idx & (F4 - 1))]; // LDS.128
                    float4 r;
                    r.x = e[it].x + cv.x; r.y = e[it].y + cv.y;
                    r.z = e[it].z + cv.z; r.w = e[it].w + cv.w;
                    __stcs(&o4[idx], r);
                }
            }
        } else {
            const int nf4 = (graphs - g0) * GPF4;
            for (int it = 0; it < GPS * GPF4 / NT; it++) {
                int idx = tid + it * NT;
                if (idx < nf4) {
                    int d   = shi[idx >> 6];
                    float4 ev = __ldcs(&eo4[idx]);
                    float4 cv = cmb4[d * F4 + (idx & (F4 - 1))];
                    float4 r;
                    r.x = ev.x + cv.x; r.y = ev.y + cv.y;
                    r.z = ev.z + cv.z; r.w = ev.w + cv.w;
                    __stcs(&o4[idx], r);
                }
            }
        }
    } else {
        // ================= GRAPH BLOCK: 8 graphs, 1 per warp =================
        // stage small tables into shared ONCE per block
        float* mul_s  = scomb;            // 100
        float* emb3_s = scomb + VV;       // 100
        float* emb4_s = scomb + 2 * VV;   // 100
        if (tid < VV)            mul_s[tid]       = __ldg(&mul[tid]);
        else if (tid < 2 * VV)   emb3_s[tid - VV] = __ldg(&emb3[tid - VV]);
        else if (tid < 3 * VV)   emb4_s[tid - 2 * VV] = __ldg(&emb4[tid - 2 * VV]);
        __syncthreads();

        const int w    = tid >> 5;
        const int lane = tid & 31;
        const int g    = rbid * GPG + w;
        if (g >= graphs) return;

        float* ds  = shf + w * VV;
        short* sim = shs + w * VV;
        short* eim = shs + GPG * VV + w * VV;
        const float* Sg = S + (size_t)g * VV;

        // symmetrize
        #pragma unroll
        for (int r = 0; r < 4; r++) {
            int e = lane + 32 * r;
            if (e < VV) {
                int ii = e / V, jj = e % V;
                ds[e] = fminf(__ldg(&Sg[e]), __ldg(&Sg[jj * V + ii]));
            }
        }
        __syncwarp();

        int   iiA[4], jjA[4];
        bool  act[4];
        float ef[4], spv[4], dsown[4];
        const float a = sqrtf(2.0f * 3.14159f);     // PI as written in source

        #pragma unroll
        for (int r = 0; r < 4; r++) {
            int e = lane + 32 * r;
            act[r] = (e < VV);
            int e2 = act[r] ? e : 0;
            iiA[r] = e2 / V; jjA[r] = e2 % V;
            spv[r] = 0.0f;
            float x = __ldg(&bias[e2]);
            #pragma unroll
            for (int m = 0; m < V; m++)
                x += ds[iiA[r] * V + m] * mul_s[m * V + jjA[r]];
            float sd = __ldg(&stds[jjA[r]]);
            float z  = __fdividef(x - __ldg(&means[jjA[r]]), sd);
            float tmp = __fdividef(__expf(-0.5f * z * z), a * sd);
            float sg  = __fdividef(1.0f, 1.0f + __expf(-tmp));
            // tanh(sg) = (e^{2sg}-1)/(e^{2sg}+1)
            float E = __expf(2.0f * sg);
            ef[r] = __fdividef(E - 1.0f, E + 1.0f);
            dsown[r] = ds[e2];
        }
        __syncwarp();

        // Floyd-Warshall with update-indicator accumulation.
        // All dists >= 0 (S in [0,1)), so iteration k never writes row k or
        // column k (the only cells it reads) -> single sync per iteration.
        #pragma unroll
        for (int k = 0; k < V; k++) {
            float dik[4], dkj[4];
            #pragma unroll
            for (int r = 0; r < 4; r++) {
                dik[r] = ds[iiA[r] * V + k];
                dkj[r] = ds[k * V + jjA[r]];
            }
            #pragma unroll
            for (int r = 0; r < 4; r++) {
                if (act[r]) {
                    float temp = dik[r] + dkj[r];
                    if (temp < dsown[r]) {          // == (new != dist)
                        dsown[r] = temp;
                        ds[lane + 32 * r] = temp;
                        spv[r] += ef[r];
                    }
                }
            }
            __syncwarp();
        }

        #pragma unroll
        for (int r = 0; r < 4; r++) {
            if (act[r]) {
                int Si = (int)dsown[r]; Si = min(max(Si, 0), V - 1);
                int Ei = (int)spv[r];   Ei = min(max(Ei, 0), V - 1);
                sim[lane + 32 * r] = (short)Si;
                eim[lane + 32 * r] = (short)Ei;
            }
        }
        __syncwarp();

        // atten_bias[g, i, c] = sum_j ( emb3[si[i,j], c] + emb4[ei[i,j], c] )
        #pragma unroll
        for (int r = 0; r < 4; r++) {
            int o = lane + 32 * r;
            if (o < VV) {
                int i2 = o / V, c = o % V;
                float acc0 = 0.0f, acc1 = 0.0f;
                #pragma unroll
                for (int j2 = 0; j2 < V; j2 += 2) {
                    acc0 += emb3_s[sim[i2 * V + j2] * V + c]
                          + emb4_s[eim[i2 * V + j2] * V + c];
                    acc1 += emb3_s[sim[i2 * V + j2 + 1] * V + c]
                          + emb4_s[eim[i2 * V + j2 + 1] * V + c];
                }
                out_att[(size_t)g * VV + o] = acc0 + acc1;
            }
        }
    }
}

extern "C" void kernel_launch(void* const* d_in, const int* in_sizes, int n_in,
                              void* d_out, int out_size)
{
    const float* end_output = (const float*)d_in[0];   // (B,T,V,F)
    const float* S          = (const float*)d_in[1];   // (B,T,V,V)
    const float* mul_       = (const float*)d_in[2];   // (V,V)
    const float* bias_      = (const float*)d_in[3];   // (V,V)
    const float* means_     = (const float*)d_in[4];   // (1,V)
    const float* stds_      = (const float*)d_in[5];   // (1,V)
    const float* emb_in_    = (const float*)d_in[6];   // (F,F)
    const float* emb_out_   = (const float*)d_in[7];   // (F,F)
    const float* emb3_      = (const float*)d_in[8];   // (V,V)
    const float* emb4_      = (const float*)d_in[9];   // (V,V)

    float* out = (float*)d_out;
    const int graphs = in_sizes[1] / VV;               // B*T
    float* out_att = out + (size_t)in_sizes[0];        // atten_bias after outputs

    int nsb = (graphs + GPS - 1) / GPS;
    int ngb = (graphs + GPG - 1) / GPG;
    int interleave = (nsb == ngb) ? 1 : 0;

    graph_embed_kernel<<<nsb + ngb, NT>>>(
        end_output, S, mul_, bias_, means_, stds_,
        emb_in_, emb_out_, emb3_, emb4_, out, out_att, graphs, nsb, interleave);
}

// round 16
// speedup vs baseline: 1.0903x; 1.0189x over previous
#include <cuda_runtime.h>
#include <cuda_bf16.h>

// Problem constants (from reference): B=128, T=200, V=10, F=256
#define V 10
#define VV 100
#define F 256
#define F4 64              // float4 per row
#define GPF4 640           // float4 per graph
#define NT 256

#define GPS 8              // graphs per streaming block (20 stream iters)
#define GPG 8              // graphs per graph block (1 per warp)

__global__ __launch_bounds__(NT, 6)
void graph_embed_kernel(const float* __restrict__ end_output,
                        const float* __restrict__ S,
                        const float* __restrict__ mul,
                        const float* __restrict__ bias,
                        const float* __restrict__ means,
                        const float* __restrict__ stds,
                        const float* __restrict__ emb_in,
                        const float* __restrict__ emb_out,
                        const float* __restrict__ emb3,
                        const float* __restrict__ emb4,
                        float* __restrict__ out,
                        float* __restrict__ out_att,
                        int graphs, int nsb, int interleave)
{
    const int bid = blockIdx.x;
    const int tid = threadIdx.x;

    __shared__ float shf[GPG * VV];      // 800 floats: S stage (stream) / dist (graph)
    __shared__ float scomb[V * F];       // stream: comb table | graph: mul/emb3/emb4 stage
    __shared__ int   shi[GPS * V];       // degrees (stream)
    __shared__ short shs[2 * GPG * VV];  // si|ei (graph)

    // role mapping: 1:1 interleave when block counts match
    int role, rbid;
    if (interleave) { role = bid & 1; rbid = bid >> 1; }
    else { if (bid < nsb) { role = 0; rbid = bid; } else { role = 1; rbid = bid - nsb; } }

    if (role == 0) {
        // ================= STREAMING BLOCK: 8 graphs =================
        const int g0 = rbid * GPS;
        const float* Sg = S + (size_t)g0 * VV;
        const int nloc = min(GPS, graphs - g0) * VV;
        for (int u = tid; u < nloc; u += NT)
            shf[u] = Sg[u];
        // build comb[d][f] = emb_in[d,f] + emb_out[d,f] (rows 0..9, L1-hot per SM)
        #pragma unroll
        for (int c = 0; c < V * F / NT; c++) {
            int u = tid + c * NT;
            scomb[u] = __ldg(&emb_in[u]) + __ldg(&emb_out[u]);
        }
        __syncthreads();
        if (tid < GPS * V) {
            int l = tid / V, v = tid % V;
            if (g0 + l < graphs) {
                const float* sl = shf + l * VV;
                float dsum = 0.0f;
                #pragma unroll
                for (int ii = 0; ii < V; ii++)
                    dsum += fminf(sl[ii * V + v], sl[v * V + ii]);
                shi[tid] = (int)dsum;               // trunc toward zero, >= 0
            }
        }
        __syncthreads();

        const float4* eo4  = (const float4*)(end_output + (size_t)g0 * (V * F));
        float4*       o4   = (float4*)(out + (size_t)g0 * (V * F));
        const float4* cmb4 = (const float4*)scomb;

        if (g0 + GPS <= graphs) {
            // fast path: 4 chunks, each front-batched with 5 loads
            float4 e[5];
            #pragma unroll
            for (int c = 0; c < 4; c++) {
                #pragma unroll
                for (int it = 0; it < 5; it++)
                    e[it] = __ldcs(&eo4[tid + (c * 5 + it) * NT]);
                #pragma unroll
                for (int it = 0; it < 5; it++) {
                    int idx = tid + (c * 5 + it) * NT;           // 0..5119
                    int d   = shi[idx >> 6];
                    float4 cv = cmb4[d * F4 + (idx & (F4 - 1))]; // LDS.128
                    float4 r;
                    r.x = e[it].x + cv.x; r.y = e[it].y + cv.y;
                    r.z = e[it].z + cv.z; r.w = e[it].w + cv.w;
                    __stcs(&o4[idx], r);
                }
            }
        } else {
            const int nf4 = (graphs - g0) * GPF4;
            for (int it = 0; it < GPS * GPF4 / NT; it++) {
                int idx = tid + it * NT;
                if (idx < nf4) {
                    int d   = shi[idx >> 6];
                    float4 ev = __ldcs(&eo4[idx]);
                    float4 cv = cmb4[d * F4 + (idx & (F4 - 1))];
                    float4 r;
                    r.x = ev.x + cv.x; r.y = ev.y + cv.y;
                    r.z = ev.z + cv.z; r.w = ev.w + cv.w;
                    __stcs(&o4[idx], r);
                }
            }
        }
    } else {
        // ================= GRAPH BLOCK: 8 graphs, 1 per warp =================
        // stage small tables into shared ONCE per block
        float* mul_s  = scomb;            // 100
        float* emb3_s = scomb + VV;       // 100
        float* emb4_s = scomb + 2 * VV;   // 100
        if (tid < VV)            mul_s[tid]       = __ldg(&mul[tid]);
        else if (tid < 2 * VV)   emb3_s[tid - VV] = __ldg(&emb3[tid - VV]);
        else if (tid < 3 * VV)   emb4_s[tid - 2 * VV] = __ldg(&emb4[tid - 2 * VV]);
        __syncthreads();

        const int w    = tid >> 5;
        const int lane = tid & 31;
        const int g    = rbid * GPG + w;
        if (g >= graphs) return;

        float* ds  = shf + w * VV;
        short* sim = shs + w * VV;
        short* eim = shs + GPG * VV + w * VV;
        const float* Sg = S + (size_t)g * VV;

        // symmetrize
        #pragma unroll
        for (int r = 0; r < 4; r++) {
            int e = lane + 32 * r;
            if (e < VV) {
                int ii = e / V, jj = e % V;
                ds[e] = fminf(__ldg(&Sg[e]), __ldg(&Sg[jj * V + ii]));
            }
        }
        __syncwarp();

        int   iiA[4], jjA[4];
        bool  act[4];
        float ef[4], spv[4], dsown[4];
        const float a = sqrtf(2.0f * 3.14159f);     // PI as written in source

        #pragma unroll
        for (int r = 0; r < 4; r++) {
            int e = lane + 32 * r;
            act[r] = (e < VV);
            int e2 = act[r] ? e : 0;
            iiA[r] = e2 / V; jjA[r] = e2 % V;
            spv[r] = 0.0f;
            float x = __ldg(&bias[e2]);
            #pragma unroll
            for (int m = 0; m < V; m++)
                x += ds[iiA[r] * V + m] * mul_s[m * V + jjA[r]];
            float sd = __ldg(&stds[jjA[r]]);
            float z  = __fdividef(x - __ldg(&means[jjA[r]]), sd);
            float tmp = __fdividef(__expf(-0.5f * z * z), a * sd);
            float sg  = __fdividef(1.0f, 1.0f + __expf(-tmp));
            // tanh(sg) = (e^{2sg}-1)/(e^{2sg}+1)
            float E = __expf(2.0f * sg);
            ef[r] = __fdividef(E - 1.0f, E + 1.0f);
            dsown[r] = ds[e2];
        }
        __syncwarp();

        // Floyd-Warshall with update-indicator accumulation.
        // All dists >= 0 (S in [0,1)), so iteration k never writes row k or
        // column k (the only cells it reads) -> single sync per iteration.
        #pragma unroll
        for (int k = 0; k < V; k++) {
            float dik[4], dkj[4];
            #pragma unroll
            for (int r = 0; r < 4; r++) {
                dik[r] = ds[iiA[r] * V + k];
                dkj[r] = ds[k * V + jjA[r]];
            }
            #pragma unroll
            for (int r = 0; r < 4; r++) {
                if (act[r]) {
                    float temp = dik[r] + dkj[r];
                    if (temp < dsown[r]) {          // == (new != dist)
                        dsown[r] = temp;
                        ds[lane + 32 * r] = temp;
                        spv[r] += ef[r];
                    }
                }
            }
            __syncwarp();
        }

        #pragma unroll
        for (int r = 0; r < 4; r++) {
            if (act[r]) {
                int Si = (int)dsown[r]; Si = min(max(Si, 0), V - 1);
                int Ei = (int)spv[r];   Ei = min(max(Ei, 0), V - 1);
                sim[lane + 32 * r] = (short)Si;
                eim[lane + 32 * r] = (short)Ei;
            }
        }
        __syncwarp();

        // atten_bias[g, i, c] = sum_j ( emb3[si[i,j], c] + emb4[ei[i,j], c] )
        #pragma unroll
        for (int r = 0; r < 4; r++) {
            int o = lane + 32 * r;
            if (o < VV) {
                int i2 = o / V, c = o % V;
                float acc0 = 0.0f, acc1 = 0.0f;
                #pragma unroll
                for (int j2 = 0; j2 < V; j2 += 2) {
                    acc0 += emb3_s[sim[i2 * V + j2] * V + c]
                          + emb4_s[eim[i2 * V + j2] * V + c];
                    acc1 += emb3_s[sim[i2 * V + j2 + 1] * V + c]
                          + emb4_s[eim[i2 * V + j2 + 1] * V + c];
                }
                out_att[(size_t)g * VV + o] = acc0 + acc1;
            }
        }
    }
}

extern "C" void kernel_launch(void* const* d_in, const int* in_sizes, int n_in,
                              void* d_out, int out_size)
{
    const float* end_output = (const float*)d_in[0];   // (B,T,V,F)
    const float* S          = (const float*)d_in[1];   // (B,T,V,V)
    const float* mul_       = (const float*)d_in[2];   // (V,V)
    const float* bias_      = (const float*)d_in[3];   // (V,V)
    const float* means_     = (const float*)d_in[4];   // (1,V)
    const float* stds_      = (const float*)d_in[5];   // (1,V)
    const float* emb_in_    = (const float*)d_in[6];   // (F,F)
    const float* emb_out_   = (const float*)d_in[7];   // (F,F)
    const float* emb3_      = (const float*)d_in[8];   // (V,V)
    const float* emb4_      = (const float*)d_in[9];   // (V,V)

    float* out = (float*)d_out;
    const int graphs = in_sizes[1] / VV;               // B*T
    float* out_att = out + (size_t)in_sizes[0];        // atten_bias after outputs

    int nsb = (graphs + GPS - 1) / GPS;
    int ngb = (graphs + GPG - 1) / GPG;
    int interleave = (nsb == ngb) ? 1 : 0;

    graph_embed_kernel<<<nsb + ngb, NT>>>(
        end_output, S, mul_, bias_, means_, stds_,
        emb_in_, emb_out_, emb3_, emb4_, out, out_att, graphs, nsb, interleave);
}